// round 1
// baseline (speedup 1.0000x reference)
#include <cuda_runtime.h>
#include <math.h>

#define BB 4
#define HH 8
#define LQ 1024
#define LK 2048
#define DM 128
#define DKH 16
#define EPSV 1e-5f

// ---------------- scratch (device globals; no runtime alloc) ----------------
__device__ float g_Q [BB*HH*LQ*DKH];   // head-major [bh][l][16]
__device__ float g_K [BB*HH*LK*DKH];
__device__ float g_V [BB*HH*LK*DKH];
__device__ float g_V2[BB*HH*LQ*DKH];
__device__ float g_o1[BB*LQ*DM];       // A@V  (model layout)
__device__ float g_o2[BB*LK*DM];       // A2@V2

// ---------------- projection: Yh[bh][l][d] = (X @ W + b) head-major ---------
__global__ __launch_bounds__(256)
void proj_kernel(const float* __restrict__ X, const float* __restrict__ W,
                 const float* __restrict__ bias, float* __restrict__ Yh, int L)
{
    extern __shared__ float sm[];
    float* Ws = sm;             // 128*128
    float* Xs = sm + DM*DM;     // 32*128
    int tid = threadIdx.x;
    int b = blockIdx.y;
    int l0 = blockIdx.x * 32;
    for (int i = tid; i < DM*DM; i += 256) Ws[i] = W[i];
    const float* xb = X + ((size_t)(b*L + l0))*DM;
    for (int i = tid; i < 32*DM; i += 256) Xs[i] = xb[i];
    __syncthreads();

    int c  = tid & 127;
    int r0 = tid >> 7;           // 0 or 1; rows r0 + 2*j
    float acc[16];
    float bv = bias[c];
#pragma unroll
    for (int j = 0; j < 16; j++) acc[j] = bv;
    for (int cc = 0; cc < DM; cc++) {
        float w = Ws[cc*DM + c];
#pragma unroll
        for (int j = 0; j < 16; j++)
            acc[j] += Xs[(r0 + 2*j)*DM + cc] * w;
    }
    int h = c >> 4, d = c & 15;
#pragma unroll
    for (int j = 0; j < 16; j++) {
        int l = l0 + r0 + 2*j;
        Yh[((size_t)(b*HH + h)*L + l)*DKH + d] = acc[j];
    }
}

// ---------------- fused scores + entmax1.5 + (A@V) --------------------------
// CTA: 16 rows of one (b,h). scores[r][c] = 0.125 * dot(RowM[r], ColM[c])
// (0.125 = (1/sqrt(16)) * 0.5 from the entmax x*0.5)
template<int LCOL>
__global__ __launch_bounds__(512)
void attn_kernel(const float* __restrict__ RowM, const float* __restrict__ ColM,
                 const float* __restrict__ Vm, float* __restrict__ Aout,
                 float* __restrict__ Omid, int Lrow)
{
    constexpr int NT = LCOL / 32;
    extern __shared__ float sm[];
    float* S  = sm;              // 16 * LCOL
    float* Ck = sm + 16*LCOL;    // 4096 floats staging (K chunk / V chunk)

    int tid  = threadIdx.x;
    int warp = tid >> 5, lane = tid & 31;
    int bh = blockIdx.z * HH + blockIdx.y;
    int r0 = blockIdx.x * 16;

    // ---- phase 1: score tile. warp -> (rowg = warp>>2 owns 4 rows, warpk = warp&3 owns k-slice)
    int warpk = warp & 3, rowg = warp >> 2;
    float qa[4][DKH];
#pragma unroll
    for (int j = 0; j < 4; j++) {
        const float* qr = RowM + ((size_t)bh*Lrow + r0 + rowg*4 + j)*DKH;
#pragma unroll
        for (int d = 0; d < DKH; d++) qa[j][d] = qr[d];
    }
    for (int kc = 0; kc < LCOL; kc += 256) {
        const float* kb = ColM + ((size_t)bh*LCOL + kc)*DKH;
        for (int i = tid; i < 256*DKH; i += 512) {
            int j = i >> 4, d = i & 15;
            Ck[d*256 + j] = kb[i];          // transposed stage [d][j]
        }
        __syncthreads();
#pragma unroll
        for (int t = 0; t < 2; t++) {
            int kl = warpk*64 + t*32 + lane;
            float s0=0.f, s1=0.f, s2=0.f, s3=0.f;
#pragma unroll
            for (int d = 0; d < DKH; d++) {
                float kv = Ck[d*256 + kl];
                s0 += qa[0][d]*kv; s1 += qa[1][d]*kv;
                s2 += qa[2][d]*kv; s3 += qa[3][d]*kv;
            }
            S[(rowg*4+0)*LCOL + kc + kl] = 0.125f*s0;
            S[(rowg*4+1)*LCOL + kc + kl] = 0.125f*s1;
            S[(rowg*4+2)*LCOL + kc + kl] = 0.125f*s2;
            S[(rowg*4+3)*LCOL + kc + kl] = 0.125f*s3;
        }
        __syncthreads();
    }

    // ---- phase 2: entmax1.5 per row (warp -> row `warp`), Newton on regs
    float xv[NT];
#pragma unroll
    for (int t = 0; t < NT; t++) xv[t] = S[warp*LCOL + lane + 32*t];
    float m = -1e30f;
#pragma unroll
    for (int t = 0; t < NT; t++) m = fmaxf(m, xv[t]);
#pragma unroll
    for (int o = 16; o > 0; o >>= 1) m = fmaxf(m, __shfl_xor_sync(0xffffffffu, m, o));
#pragma unroll
    for (int t = 0; t < NT; t++) xv[t] -= m;

    // init: full-support closed form (exact when support == n)
    float s1r = 0.f, s2r = 0.f;
#pragma unroll
    for (int t = 0; t < NT; t++) { s1r += xv[t]; s2r += xv[t]*xv[t]; }
#pragma unroll
    for (int o = 16; o > 0; o >>= 1) {
        s1r += __shfl_xor_sync(0xffffffffu, s1r, o);
        s2r += __shfl_xor_sync(0xffffffffu, s2r, o);
    }
    const float n = (float)LCOL;
    float mean = s1r / n;
    float var  = s2r / n - mean*mean;
    float delta = (1.f - n*var) / n;
    float tau = mean - sqrtf(fmaxf(delta, 0.f));
    tau = fmaxf(tau, -1.0f);
    tau = fminf(tau, -1e-9f);

    // Newton on F(tau) = sum relu(x-tau)^2 - 1 (convex, decreasing)
    for (int it = 0; it < 50; it++) {
        float F = 0.f, G = 0.f;
#pragma unroll
        for (int t = 0; t < NT; t++) {
            float dmx = fmaxf(xv[t] - tau, 0.f);
            F += dmx*dmx; G += dmx;
        }
#pragma unroll
        for (int o = 16; o > 0; o >>= 1) {
            F += __shfl_xor_sync(0xffffffffu, F, o);
            G += __shfl_xor_sync(0xffffffffu, G, o);
        }
        float step = (F - 1.f) / (2.f*G);
        tau += step;
        tau = fmaxf(tau, -1.0f);
        if (fabsf(step) < 1e-7f) break;
    }

    // write p = relu(x-tau)^2 to A (gmem) and back into S (for AV)
    float* Arow = Aout + ((size_t)bh*Lrow + r0 + warp)*LCOL;
#pragma unroll
    for (int t = 0; t < NT; t++) {
        float dmx = fmaxf(xv[t] - tau, 0.f);
        float p = dmx*dmx;
        S[warp*LCOL + lane + 32*t] = p;
        Arow[lane + 32*t] = p;
    }
    __syncthreads();

    // ---- phase 3: Omid[row][h*16 + 0..15] = sum_k p[k] * V[k][:]
    int q  = warp;
    int dg = lane >> 3;        // 0..3 -> d = dg*4 .. dg*4+3
    int ks = lane & 7;         // k-slice
    float a0=0.f, a1=0.f, a2=0.f, a3=0.f;
    for (int kc = 0; kc < LCOL; kc += 256) {
        const float* vb = Vm + ((size_t)bh*LCOL + kc)*DKH;
        for (int i = tid; i < 4096; i += 512) Ck[i] = vb[i];   // row-major [j][16]
        __syncthreads();
        for (int kl = ks; kl < 256; kl += 8) {
            float p = S[q*LCOL + kc + kl];
            float4 v = *reinterpret_cast<const float4*>(&Ck[kl*DKH + dg*4]);
            a0 += p*v.x; a1 += p*v.y; a2 += p*v.z; a3 += p*v.w;
        }
        __syncthreads();
    }
#pragma unroll
    for (int o = 4; o > 0; o >>= 1) {
        a0 += __shfl_xor_sync(0xffffffffu, a0, o);
        a1 += __shfl_xor_sync(0xffffffffu, a1, o);
        a2 += __shfl_xor_sync(0xffffffffu, a2, o);
        a3 += __shfl_xor_sync(0xffffffffu, a3, o);
    }
    if (ks == 0) {
        int b = blockIdx.z, h = blockIdx.y;
        float4 o4 = make_float4(a0, a1, a2, a3);
        *reinterpret_cast<float4*>(
            &Omid[((size_t)(b*Lrow + r0 + q))*DM + h*DKH + dg*4]) = o4;
    }
}

// ---------------- final: relu(LN(X@WO + bO + R@WR)) --------------------------
__global__ __launch_bounds__(256)
void final_kernel(const float* __restrict__ Xmid, const float* __restrict__ Resid,
                  const float* __restrict__ WO, const float* __restrict__ bO,
                  const float* __restrict__ WR,
                  const float* __restrict__ gamma, const float* __restrict__ beta,
                  float* __restrict__ dst)
{
    extern __shared__ float sm[];
    float* Wo = sm;             // 16384
    float* Wr = sm + 16384;     // 16384
    float* Xs = sm + 32768;     // 4096
    float* Rs = sm + 36864;     // 4096
    float* Ys = sm + 40960;     // 4096
    int tid = threadIdx.x;
    size_t row0 = (size_t)blockIdx.x * 32;
    for (int i = tid; i < 16384; i += 256) { Wo[i] = WO[i]; Wr[i] = WR[i]; }
    const float* xb = Xmid  + row0*DM;
    const float* rb = Resid + row0*DM;
    for (int i = tid; i < 4096; i += 256) { Xs[i] = xb[i]; Rs[i] = rb[i]; }
    __syncthreads();

    int c  = tid & 127;
    int r0 = tid >> 7;
    float acc[16];
    float bv = bO[c];
#pragma unroll
    for (int j = 0; j < 16; j++) acc[j] = bv;
    for (int cc = 0; cc < DM; cc++) {
        float wo = Wo[cc*DM + c], wr = Wr[cc*DM + c];
#pragma unroll
        for (int j = 0; j < 16; j++) {
            int r = r0 + 2*j;
            acc[j] += Xs[r*DM + cc]*wo + Rs[r*DM + cc]*wr;
        }
    }
#pragma unroll
    for (int j = 0; j < 16; j++) Ys[(r0 + 2*j)*DM + c] = acc[j];
    __syncthreads();

    int warp = tid >> 5, lane = tid & 31;
    for (int rr = warp; rr < 32; rr += 8) {
        float v0 = Ys[rr*DM + lane],      v1 = Ys[rr*DM + lane + 32];
        float v2 = Ys[rr*DM + lane + 64], v3 = Ys[rr*DM + lane + 96];
        float s = v0 + v1 + v2 + v3;
#pragma unroll
        for (int o = 16; o > 0; o >>= 1) s += __shfl_xor_sync(0xffffffffu, s, o);
        float mu = s * (1.f/128.f);
        float d0 = v0-mu, d1 = v1-mu, d2 = v2-mu, d3 = v3-mu;
        float vs = d0*d0 + d1*d1 + d2*d2 + d3*d3;
#pragma unroll
        for (int o = 16; o > 0; o >>= 1) vs += __shfl_xor_sync(0xffffffffu, vs, o);
        float inv = rsqrtf(vs * (1.f/128.f) + EPSV);
        float* drow = dst + (row0 + rr)*DM;
        drow[lane]      = fmaxf(gamma[lane]     *d0*inv + beta[lane],      0.f);
        drow[lane + 32] = fmaxf(gamma[lane + 32]*d1*inv + beta[lane + 32], 0.f);
        drow[lane + 64] = fmaxf(gamma[lane + 64]*d2*inv + beta[lane + 64], 0.f);
        drow[lane + 96] = fmaxf(gamma[lane + 96]*d3*inv + beta[lane + 96], 0.f);
    }
}

// ---------------- host launcher ----------------------------------------------
extern "C" void kernel_launch(void* const* d_in, const int* in_sizes, int n_in,
                              void* d_out, int out_size)
{
    const float* q    = (const float*)d_in[0];
    const float* k    = (const float*)d_in[1];
    const float* v    = (const float*)d_in[2];
    const float* v2   = (const float*)d_in[3];
    const float* W_Q  = (const float*)d_in[4];
    const float* b_Q  = (const float*)d_in[5];
    const float* W_K  = (const float*)d_in[6];
    const float* b_K  = (const float*)d_in[7];
    const float* W_V  = (const float*)d_in[8];
    const float* b_V  = (const float*)d_in[9];
    const float* W_V2 = (const float*)d_in[10];
    const float* b_V2 = (const float*)d_in[11];
    const float* W_O  = (const float*)d_in[12];
    const float* b_O  = (const float*)d_in[13];
    const float* W_O2 = (const float*)d_in[14];
    const float* b_O2 = (const float*)d_in[15];
    const float* W_R  = (const float*)d_in[16];
    const float* W_R2 = (const float*)d_in[17];
    const float* gamma= (const float*)d_in[18];
    const float* beta = (const float*)d_in[19];
    float* out = (float*)d_out;

    float *pQ, *pK, *pV, *pV2, *po1, *po2;
    cudaGetSymbolAddress((void**)&pQ,  g_Q);
    cudaGetSymbolAddress((void**)&pK,  g_K);
    cudaGetSymbolAddress((void**)&pV,  g_V);
    cudaGetSymbolAddress((void**)&pV2, g_V2);
    cudaGetSymbolAddress((void**)&po1, g_o1);
    cudaGetSymbolAddress((void**)&po2, g_o2);

    const int PROJ_SMEM = (DM*DM + 32*DM) * 4;            // 81920
    const int ATT1_SMEM = (16*LK + 4096) * 4;             // 147456
    const int ATT2_SMEM = (16*LQ + 4096) * 4;             // 81920
    const int FIN_SMEM  = (2*16384 + 3*4096) * 4;         // 180224
    cudaFuncSetAttribute(proj_kernel,      cudaFuncAttributeMaxDynamicSharedMemorySize, PROJ_SMEM);
    cudaFuncSetAttribute(attn_kernel<LK>,  cudaFuncAttributeMaxDynamicSharedMemorySize, ATT1_SMEM);
    cudaFuncSetAttribute(attn_kernel<LQ>,  cudaFuncAttributeMaxDynamicSharedMemorySize, ATT2_SMEM);
    cudaFuncSetAttribute(final_kernel,     cudaFuncAttributeMaxDynamicSharedMemorySize, FIN_SMEM);

    // projections (head-major)
    proj_kernel<<<dim3(LQ/32, BB), 256, PROJ_SMEM>>>(q,  W_Q,  b_Q,  pQ,  LQ);
    proj_kernel<<<dim3(LK/32, BB), 256, PROJ_SMEM>>>(k,  W_K,  b_K,  pK,  LK);
    proj_kernel<<<dim3(LK/32, BB), 256, PROJ_SMEM>>>(v,  W_V,  b_V,  pV,  LK);
    proj_kernel<<<dim3(LQ/32, BB), 256, PROJ_SMEM>>>(v2, W_V2, b_V2, pV2, LQ);

    // d_out layout: out [B,Lq,128] | out2 [B,Lk,128] | A [B,H,Lq,Lk] | A2 [B,H,Lk,Lq]
    float* Aout  = out + ((size_t)BB*LQ*DM + (size_t)BB*LK*DM);
    float* A2out = Aout + (size_t)BB*HH*LQ*LK;

    attn_kernel<LK><<<dim3(LQ/16, HH, BB), 512, ATT1_SMEM>>>(pQ, pK, pV,  Aout,  po1, LQ);
    attn_kernel<LQ><<<dim3(LK/16, HH, BB), 512, ATT2_SMEM>>>(pK, pQ, pV2, A2out, po2, LK);

    final_kernel<<<BB*LQ/32, 256, FIN_SMEM>>>(po1, q, W_O,  b_O,  W_R,  gamma, beta, out);
    final_kernel<<<BB*LK/32, 256, FIN_SMEM>>>(po2, k, W_O2, b_O2, W_R2, gamma, beta,
                                              out + (size_t)BB*LQ*DM);
}

// round 2
// speedup vs baseline: 1.4095x; 1.4095x over previous
#include <cuda_runtime.h>
#include <math.h>

#define BB 4
#define HH 8
#define LQ 1024
#define LK 2048
#define DM 128
#define EPSV 1e-5f

// ---------------- scratch (device globals; no runtime alloc) ----------------
__device__ float g_Q [BB*HH*LQ*16];   // head-major [bh][l][16]
__device__ float g_K [BB*HH*LK*16];
__device__ float g_V [BB*HH*LK*16];
__device__ float g_V2[BB*HH*LQ*16];
__device__ float g_o1[BB*LQ*DM];
__device__ float g_o2[BB*LK*DM];

// swizzled word index of float4 #q (q=0..3) in staged row k (16 floats/row)
__device__ __forceinline__ int swz4(int k, int q) {
    return (k << 4) + (((q ^ (k >> 1)) & 3) << 2);
}

// ---------------- projection: Yh[bh][l][d] = (X @ W + b) head-major ---------
__global__ __launch_bounds__(256)
void proj_kernel(const float* __restrict__ X, const float* __restrict__ W,
                 const float* __restrict__ bias, float* __restrict__ Yh, int L)
{
    extern __shared__ float sm[];
    float* Ws = sm;               // 128 x 132 (transposed, padded)
    float* Xs = sm + 128*132;     // 16 x 128
    int tid = threadIdx.x;
    int b = blockIdx.y;
    int l0 = blockIdx.x * 16;

    // W[cc][c] -> Ws[c][cc]
    for (int i = tid; i < 128*128; i += 256) {
        int cc = i >> 7, c = i & 127;
        Ws[c*132 + cc] = W[i];
    }
    const float4* xb = (const float4*)(X + ((size_t)(b*L + l0))*DM);
    float4* Xs4 = (float4*)Xs;
    for (int i = tid; i < 16*32; i += 256) Xs4[i] = xb[i];
    __syncthreads();

    int c  = tid & 127;
    int r0 = tid >> 7;             // rows r0 + 2*j, j<8
    float acc[8];
    float bv = bias[c];
#pragma unroll
    for (int j = 0; j < 8; j++) acc[j] = bv;
    for (int cc = 0; cc < 128; cc += 4) {
        float4 w4 = *(const float4*)&Ws[c*132 + cc];
#pragma unroll
        for (int j = 0; j < 8; j++) {
            float4 x4 = *(const float4*)&Xs[(r0 + 2*j)*128 + cc];
            float a = acc[j];
            a = fmaf(x4.x, w4.x, a);
            a = fmaf(x4.y, w4.y, a);
            a = fmaf(x4.z, w4.z, a);
            a = fmaf(x4.w, w4.w, a);
            acc[j] = a;
        }
    }
    int h = c >> 4, d = c & 15;
#pragma unroll
    for (int j = 0; j < 8; j++) {
        int l = l0 + r0 + 2*j;
        Yh[((size_t)(b*HH + h)*L + l)*16 + d] = acc[j];
    }
}

// ---------------- fused scores + entmax1.5 + (A@V) --------------------------
// scores[r][c] = 0.125 * dot(Row[r], Col[c])  (0.125 = 1/sqrt(16) * 0.5)
template<int LCOL, int ROWS, int THREADS>
__global__ __launch_bounds__(THREADS)
void attn_kernel(const float* __restrict__ RowM, const float* __restrict__ ColM,
                 const float* __restrict__ Vm, float* __restrict__ Aout,
                 float* __restrict__ Omid, int Lrow)
{
    constexpr int NT   = LCOL / 32;
    constexpr int NW   = THREADS / 32;   // == ROWS
    constexpr int KS   = 2;              // column slices per row-group
    constexpr int TSTEP = 256 / KS / 32; // 4
    extern __shared__ float sm[];
    float* S  = sm;                      // ROWS * LCOL
    float* Ck = sm + ROWS*LCOL;          // 4096 floats, swizzled [256 x 16]

    int tid = threadIdx.x, warp = tid >> 5, lane = tid & 31;
    int bh = blockIdx.z * HH + blockIdx.y;
    int r0 = blockIdx.x * ROWS;

    // ---- phase 1: score tile (2-row register sharing, swizzled K stage) ----
    {
        int rowg = warp >> 1, ks1 = warp & 1;
        float qa[2][16];
#pragma unroll
        for (int j = 0; j < 2; j++) {
            int rr = r0 + rowg*2 + j; if (rr > Lrow - 1) rr = Lrow - 1;
            const float4* qr = (const float4*)(RowM + ((size_t)bh*Lrow + rr)*16);
            float4 a = qr[0], bq = qr[1], cq = qr[2], dq = qr[3];
            qa[j][0]=a.x;  qa[j][1]=a.y;  qa[j][2]=a.z;  qa[j][3]=a.w;
            qa[j][4]=bq.x; qa[j][5]=bq.y; qa[j][6]=bq.z; qa[j][7]=bq.w;
            qa[j][8]=cq.x; qa[j][9]=cq.y; qa[j][10]=cq.z;qa[j][11]=cq.w;
            qa[j][12]=dq.x;qa[j][13]=dq.y;qa[j][14]=dq.z;qa[j][15]=dq.w;
        }
        for (int kc = 0; kc < LCOL; kc += 256) {
            const float* kb = ColM + ((size_t)bh*LCOL + kc)*16;
            for (int i = tid; i < 4096; i += THREADS) {
                int j = i >> 4, d = i & 15;
                Ck[(j<<4) + ((((d>>2) ^ (j>>1)) & 3)<<2) + (d&3)] = kb[i];
            }
            __syncthreads();
#pragma unroll
            for (int t = 0; t < TSTEP; t++) {
                int kl = ks1*128 + t*32 + lane;
                float4 k0 = *(const float4*)&Ck[swz4(kl,0)];
                float4 k1 = *(const float4*)&Ck[swz4(kl,1)];
                float4 k2 = *(const float4*)&Ck[swz4(kl,2)];
                float4 k3 = *(const float4*)&Ck[swz4(kl,3)];
                float kv[16] = {k0.x,k0.y,k0.z,k0.w, k1.x,k1.y,k1.z,k1.w,
                                k2.x,k2.y,k2.z,k2.w, k3.x,k3.y,k3.z,k3.w};
                float s0 = 0.f, s1 = 0.f;
#pragma unroll
                for (int d = 0; d < 16; d++) {
                    s0 = fmaf(qa[0][d], kv[d], s0);
                    s1 = fmaf(qa[1][d], kv[d], s1);
                }
                S[(rowg*2+0)*LCOL + kc + kl] = 0.125f*s0;
                S[(rowg*2+1)*LCOL + kc + kl] = 0.125f*s1;
            }
            __syncthreads();
        }
    }

    // ---- phase 2: entmax1.5 per row (warp = row), Newton on registers ------
    {
        float xv[NT];
#pragma unroll
        for (int t = 0; t < NT; t++) xv[t] = S[warp*LCOL + lane + 32*t];
        float m = -1e30f;
#pragma unroll
        for (int t = 0; t < NT; t++) m = fmaxf(m, xv[t]);
#pragma unroll
        for (int o = 16; o > 0; o >>= 1) m = fmaxf(m, __shfl_xor_sync(0xffffffffu, m, o));
#pragma unroll
        for (int t = 0; t < NT; t++) xv[t] -= m;

        // init: full-support closed form
        float s1r = 0.f, s2r = 0.f;
#pragma unroll
        for (int t = 0; t < NT; t++) { s1r += xv[t]; s2r = fmaf(xv[t], xv[t], s2r); }
#pragma unroll
        for (int o = 16; o > 0; o >>= 1) {
            s1r += __shfl_xor_sync(0xffffffffu, s1r, o);
            s2r += __shfl_xor_sync(0xffffffffu, s2r, o);
        }
        const float n = (float)LCOL;
        float mean = s1r / n;
        float var  = s2r / n - mean*mean;
        float delta = (1.f - n*var) / n;
        float tau = mean - sqrtf(fmaxf(delta, 0.f));
        tau = fmaxf(tau, -1.0f);
        tau = fminf(tau, -1e-9f);

        // Newton on F(tau) = sum relu(x-tau)^2 - 1 (convex, decreasing)
        for (int it = 0; it < 40; it++) {
            float F = 0.f, G = 0.f;
#pragma unroll
            for (int t = 0; t < NT; t++) {
                float dmx = fmaxf(xv[t] - tau, 0.f);
                F = fmaf(dmx, dmx, F); G += dmx;
            }
#pragma unroll
            for (int o = 16; o > 0; o >>= 1) {
                F += __shfl_xor_sync(0xffffffffu, F, o);
                G += __shfl_xor_sync(0xffffffffu, G, o);
            }
            float step = (F - 1.f) / (2.f*G);
            tau += step;
            tau = fmaxf(tau, -1.0f);
            if (fabsf(step) < 1e-7f) break;
        }

        int row = r0 + warp;
        bool ok = row < Lrow;
        float* Arow = Aout + ((size_t)bh*Lrow + (ok ? row : 0))*LCOL;
#pragma unroll
        for (int t = 0; t < NT; t++) {
            float dmx = fmaxf(xv[t] - tau, 0.f);
            float p = dmx*dmx;
            S[warp*LCOL + lane + 32*t] = p;
            if (ok) Arow[lane + 32*t] = p;
        }
    }

    // ---- phase 3: O[row][d] = sum_k p[k] V[k][d] (warp = row, swizzled V) --
    {
        float o[16];
#pragma unroll
        for (int d = 0; d < 16; d++) o[d] = 0.f;
        for (int kc = 0; kc < LCOL; kc += 256) {
            const float* vb = Vm + ((size_t)bh*LCOL + kc)*16;
            for (int i = tid; i < 4096; i += THREADS) {
                int j = i >> 4, d = i & 15;
                Ck[(j<<4) + ((((d>>2) ^ (j>>1)) & 3)<<2) + (d&3)] = vb[i];
            }
            __syncthreads();
#pragma unroll
            for (int t = 0; t < 8; t++) {
                int kl = t*32 + lane;
                float p = S[warp*LCOL + kc + kl];
                float4 v0 = *(const float4*)&Ck[swz4(kl,0)];
                float4 v1 = *(const float4*)&Ck[swz4(kl,1)];
                float4 v2 = *(const float4*)&Ck[swz4(kl,2)];
                float4 v3 = *(const float4*)&Ck[swz4(kl,3)];
                o[0]  = fmaf(p, v0.x, o[0]);  o[1]  = fmaf(p, v0.y, o[1]);
                o[2]  = fmaf(p, v0.z, o[2]);  o[3]  = fmaf(p, v0.w, o[3]);
                o[4]  = fmaf(p, v1.x, o[4]);  o[5]  = fmaf(p, v1.y, o[5]);
                o[6]  = fmaf(p, v1.z, o[6]);  o[7]  = fmaf(p, v1.w, o[7]);
                o[8]  = fmaf(p, v2.x, o[8]);  o[9]  = fmaf(p, v2.y, o[9]);
                o[10] = fmaf(p, v2.z, o[10]); o[11] = fmaf(p, v2.w, o[11]);
                o[12] = fmaf(p, v3.x, o[12]); o[13] = fmaf(p, v3.y, o[13]);
                o[14] = fmaf(p, v3.z, o[14]); o[15] = fmaf(p, v3.w, o[15]);
            }
            __syncthreads();
        }
        float res = 0.f;
#pragma unroll
        for (int d = 0; d < 16; d++) {
            float s = o[d];
#pragma unroll
            for (int off = 16; off > 0; off >>= 1)
                s += __shfl_xor_sync(0xffffffffu, s, off);
            if (lane == d) res = s;
        }
        int row = r0 + warp;
        if (lane < 16 && row < Lrow) {
            int b = blockIdx.z, h = blockIdx.y;
            Omid[((size_t)(b*Lrow + row))*DM + h*16 + lane] = res;
        }
    }
}

// ---------------- final: relu(LN(X@WO + bO + R@WR)) --------------------------
__global__ __launch_bounds__(256)
void final_kernel(const float* __restrict__ Xmid, const float* __restrict__ Resid,
                  const float* __restrict__ WO, const float* __restrict__ bO,
                  const float* __restrict__ WR,
                  const float* __restrict__ gamma, const float* __restrict__ beta,
                  float* __restrict__ dst)
{
    extern __shared__ float sm[];
    float* Wo = sm;             // 16384
    float* Wr = sm + 16384;     // 16384
    float* Xs = sm + 32768;     // 4096
    float* Rs = sm + 36864;     // 4096
    float* Ys = sm + 40960;     // 4096
    int tid = threadIdx.x;
    size_t row0 = (size_t)blockIdx.x * 32;
    for (int i = tid; i < 16384; i += 256) { Wo[i] = WO[i]; Wr[i] = WR[i]; }
    const float* xb = Xmid  + row0*DM;
    const float* rb = Resid + row0*DM;
    for (int i = tid; i < 4096; i += 256) { Xs[i] = xb[i]; Rs[i] = rb[i]; }
    __syncthreads();

    int c  = tid & 127;
    int r0 = tid >> 7;
    float acc[16];
    float bv = bO[c];
#pragma unroll
    for (int j = 0; j < 16; j++) acc[j] = bv;
    for (int cc = 0; cc < DM; cc++) {
        float wo = Wo[cc*DM + c], wr = Wr[cc*DM + c];
#pragma unroll
        for (int j = 0; j < 16; j++) {
            int r = r0 + 2*j;
            acc[j] += Xs[r*DM + cc]*wo + Rs[r*DM + cc]*wr;
        }
    }
#pragma unroll
    for (int j = 0; j < 16; j++) Ys[(r0 + 2*j)*DM + c] = acc[j];
    __syncthreads();

    int warp = tid >> 5, lane = tid & 31;
    for (int rr = warp; rr < 32; rr += 8) {
        float v0 = Ys[rr*DM + lane],      v1 = Ys[rr*DM + lane + 32];
        float v2 = Ys[rr*DM + lane + 64], v3 = Ys[rr*DM + lane + 96];
        float s = v0 + v1 + v2 + v3;
#pragma unroll
        for (int o = 16; o > 0; o >>= 1) s += __shfl_xor_sync(0xffffffffu, s, o);
        float mu = s * (1.f/128.f);
        float d0 = v0-mu, d1 = v1-mu, d2 = v2-mu, d3 = v3-mu;
        float vs = d0*d0 + d1*d1 + d2*d2 + d3*d3;
#pragma unroll
        for (int o = 16; o > 0; o >>= 1) vs += __shfl_xor_sync(0xffffffffu, vs, o);
        float inv = rsqrtf(vs * (1.f/128.f) + EPSV);
        float* drow = dst + (row0 + rr)*DM;
        drow[lane]      = fmaxf(gamma[lane]     *d0*inv + beta[lane],      0.f);
        drow[lane + 32] = fmaxf(gamma[lane + 32]*d1*inv + beta[lane + 32], 0.f);
        drow[lane + 64] = fmaxf(gamma[lane + 64]*d2*inv + beta[lane + 64], 0.f);
        drow[lane + 96] = fmaxf(gamma[lane + 96]*d3*inv + beta[lane + 96], 0.f);
    }
}

// ---------------- host launcher ----------------------------------------------
extern "C" void kernel_launch(void* const* d_in, const int* in_sizes, int n_in,
                              void* d_out, int out_size)
{
    const float* q    = (const float*)d_in[0];
    const float* k    = (const float*)d_in[1];
    const float* v    = (const float*)d_in[2];
    const float* v2   = (const float*)d_in[3];
    const float* W_Q  = (const float*)d_in[4];
    const float* b_Q  = (const float*)d_in[5];
    const float* W_K  = (const float*)d_in[6];
    const float* b_K  = (const float*)d_in[7];
    const float* W_V  = (const float*)d_in[8];
    const float* b_V  = (const float*)d_in[9];
    const float* W_V2 = (const float*)d_in[10];
    const float* b_V2 = (const float*)d_in[11];
    const float* W_O  = (const float*)d_in[12];
    const float* b_O  = (const float*)d_in[13];
    const float* W_O2 = (const float*)d_in[14];
    const float* b_O2 = (const float*)d_in[15];
    const float* W_R  = (const float*)d_in[16];
    const float* W_R2 = (const float*)d_in[17];
    const float* gamma= (const float*)d_in[18];
    const float* beta = (const float*)d_in[19];
    float* out = (float*)d_out;

    float *pQ, *pK, *pV, *pV2, *po1, *po2;
    cudaGetSymbolAddress((void**)&pQ,  g_Q);
    cudaGetSymbolAddress((void**)&pK,  g_K);
    cudaGetSymbolAddress((void**)&pV,  g_V);
    cudaGetSymbolAddress((void**)&pV2, g_V2);
    cudaGetSymbolAddress((void**)&po1, g_o1);
    cudaGetSymbolAddress((void**)&po2, g_o2);

    const int PROJ_SMEM = (128*132 + 16*128) * 4;          // 75776
    const int ATT1_SMEM = (20*LK + 4096) * 4;              // 180224
    const int ATT2_SMEM = (32*LQ + 4096) * 4;              // 147456
    const int FIN_SMEM  = (2*16384 + 3*4096) * 4;          // 180224
    cudaFuncSetAttribute(proj_kernel,  cudaFuncAttributeMaxDynamicSharedMemorySize, PROJ_SMEM);
    cudaFuncSetAttribute(attn_kernel<LK, 20, 640>,  cudaFuncAttributeMaxDynamicSharedMemorySize, ATT1_SMEM);
    cudaFuncSetAttribute(attn_kernel<LQ, 32, 1024>, cudaFuncAttributeMaxDynamicSharedMemorySize, ATT2_SMEM);
    cudaFuncSetAttribute(final_kernel, cudaFuncAttributeMaxDynamicSharedMemorySize, FIN_SMEM);

    proj_kernel<<<dim3(LQ/16, BB), 256, PROJ_SMEM>>>(q,  W_Q,  b_Q,  pQ,  LQ);
    proj_kernel<<<dim3(LK/16, BB), 256, PROJ_SMEM>>>(k,  W_K,  b_K,  pK,  LK);
    proj_kernel<<<dim3(LK/16, BB), 256, PROJ_SMEM>>>(v,  W_V,  b_V,  pV,  LK);
    proj_kernel<<<dim3(LQ/16, BB), 256, PROJ_SMEM>>>(v2, W_V2, b_V2, pV2, LQ);

    // d_out layout: out [B,Lq,128] | out2 [B,Lk,128] | A [B,H,Lq,Lk] | A2 [B,H,Lk,Lq]
    float* Aout  = out + ((size_t)BB*LQ*DM + (size_t)BB*LK*DM);
    float* A2out = Aout + (size_t)BB*HH*LQ*LK;

    attn_kernel<LK, 20, 640><<<dim3((LQ + 19)/20, HH, BB), 640, ATT1_SMEM>>>(
        pQ, pK, pV,  Aout,  po1, LQ);
    attn_kernel<LQ, 32, 1024><<<dim3(LK/32, HH, BB), 1024, ATT2_SMEM>>>(
        pK, pQ, pV2, A2out, po2, LK);

    final_kernel<<<BB*LQ/32, 256, FIN_SMEM>>>(po1, q, W_O,  b_O,  W_R,  gamma, beta, out);
    final_kernel<<<BB*LK/32, 256, FIN_SMEM>>>(po2, k, W_O2, b_O2, W_R2, gamma, beta,
                                              out + (size_t)BB*LQ*DM);
}